// round 16
// baseline (speedup 1.0000x reference)
#include <cuda_runtime.h>
#include <cuda_bf16.h>
#include <math.h>
#include <stdint.h>

// B=4, N_TR=256, M_DET=1024, T=16, D=256, H=4, HD=64, N_FUSER=4, N_GNN=12, ITERS=100
#define P_TRK 16384
#define P_DET 4096
#define P_TR  1024
#define P_TD  5120
#define ZROW  263425
#define NORM_C  (-7.1546153569136625f)
#define LOG1024 6.931471805599453f
#define LOG256  5.545177444479562f
#define NBLK_SINK 148

__device__ float g_pool[100000000];

// ---------------------------------------------------------------------------
// mma / ldmatrix / cp.async wrappers
// ---------------------------------------------------------------------------
__device__ __forceinline__ void mma_bf16(float* c, const uint32_t* a, const uint32_t* b)
{
    asm volatile(
        "mma.sync.aligned.m16n8k16.row.col.f32.bf16.bf16.f32 "
        "{%0,%1,%2,%3}, {%4,%5,%6,%7}, {%8,%9}, {%0,%1,%2,%3};"
        : "+f"(c[0]), "+f"(c[1]), "+f"(c[2]), "+f"(c[3])
        : "r"(a[0]), "r"(a[1]), "r"(a[2]), "r"(a[3]), "r"(b[0]), "r"(b[1]));
}
#define LDSM4(r, a) \
    asm volatile("ldmatrix.sync.aligned.m8n8.x4.shared.b16 {%0,%1,%2,%3}, [%4];" \
                 : "=r"((r)[0]), "=r"((r)[1]), "=r"((r)[2]), "=r"((r)[3]) : "r"(a))
#define LDSM2(r, a) \
    asm volatile("ldmatrix.sync.aligned.m8n8.x2.shared.b16 {%0,%1}, [%2];" \
                 : "=r"((r)[0]), "=r"((r)[1]) : "r"(a))
__device__ __forceinline__ void cpa16(uint32_t dst, const void* src)
{
    asm volatile("cp.async.ca.shared.global [%0], [%1], 16;" :: "r"(dst), "l"(src));
}

// ---------------------------------------------------------------------------
// bf16x2 tensor GEMM (R8/R11 body, 1 CTA/SM)
// ---------------------------------------------------------------------------
__global__ __launch_bounds__(256, 1) void gemm_bf2_k(
    const __nv_bfloat16* __restrict__ Whi, const __nv_bfloat16* __restrict__ Wlo,
    const float* __restrict__ bias,
    const __nv_bfloat16* __restrict__ Xh, const __nv_bfloat16* __restrict__ Xl,
    const __nv_bfloat16* __restrict__ X2h, const __nv_bfloat16* __restrict__ X2l,
    int xs, int x2s,
    const float* __restrict__ addp, int as,
    float* __restrict__ out, int os,
    __nv_bfloat16* __restrict__ oTh, __nv_bfloat16* __restrict__ oTl, int ots,
    int outOff, int I, int relu)
{
    extern __shared__ char sm[];
    uint32_t sb = (uint32_t)__cvta_generic_to_shared(sm);
    int tid = threadIdx.x, warp = tid >> 5, lane = tid & 31;
    int warpO = warp >> 2, warpP = warp & 3;
    int pc = blockIdx.x * 128, oc = blockIdx.y * 128;
    int lrow = tid >> 1, lhalf = tid & 1;
    int nch = I >> 5;

    auto issue = [&](int c, int st) {
        uint32_t stb = sb + st * 32768;
        int kc = c * 32;
        int sw = (lrow >> 1) & 3;
        uint32_t s0 = (uint32_t)(((lhalf * 2 + 0) ^ sw) << 4);
        uint32_t s1 = (uint32_t)(((lhalf * 2 + 1) ^ sw) << 4);
        {
            const __nv_bfloat16* sh = Whi + (size_t)(oc + lrow) * I + kc + lhalf * 16;
            const __nv_bfloat16* sl = Wlo + (size_t)(oc + lrow) * I + kc + lhalf * 16;
            uint32_t rb = stb + lrow * 64;
            cpa16(rb + s0, sh); cpa16(rb + s1, sh + 8);
            cpa16(rb + 8192 + s0, sl); cpa16(rb + 8192 + s1, sl + 8);
        }
        {
            const __nv_bfloat16 *sh, *sl;
            if (X2h != nullptr && kc >= 256) {
                sh = X2h + (size_t)(pc + lrow) * x2s + (kc - 256) + lhalf * 16;
                sl = X2l + (size_t)(pc + lrow) * x2s + (kc - 256) + lhalf * 16;
            } else {
                sh = Xh + (size_t)(pc + lrow) * xs + kc + lhalf * 16;
                sl = Xl + (size_t)(pc + lrow) * xs + kc + lhalf * 16;
            }
            uint32_t rb = stb + 16384 + lrow * 64;
            cpa16(rb + s0, sh); cpa16(rb + s1, sh + 8);
            cpa16(rb + 8192 + s0, sl); cpa16(rb + 8192 + s1, sl + 8);
        }
        asm volatile("cp.async.commit_group;" ::: "memory");
    };

    issue(0, 0);
    if (nch > 1) issue(1, 1);

    float acc[4][4][4];
#pragma unroll
    for (int mt = 0; mt < 4; mt++)
#pragma unroll
        for (int nt = 0; nt < 4; nt++)
#pragma unroll
            for (int i = 0; i < 4; i++) acc[mt][nt][i] = 0.f;

    int lane8 = lane & 7, g1 = (lane >> 3) & 1, g2 = lane >> 4;

    for (int c = 0; c < nch; c++) {
        if (c < nch - 1) asm volatile("cp.async.wait_group 1;" ::: "memory");
        else             asm volatile("cp.async.wait_group 0;" ::: "memory");
        __syncthreads();
        if (c + 2 < nch) issue(c + 2, (c + 2) % 3);
        uint32_t stb = sb + (c % 3) * 32768;
#pragma unroll
        for (int s = 0; s < 2; s++) {
            uint32_t ah[4][4], al_[4][4], bh[4][2], bl[4][2];
#pragma unroll
            for (int mt = 0; mt < 4; mt++) {
                int row = warpO * 64 + mt * 16 + lane8 + g1 * 8;
                uint32_t ad = stb + row * 64 + ((((s << 1) | g2) ^ ((row >> 1) & 3)) << 4);
                LDSM4(ah[mt], ad);
                LDSM4(al_[mt], ad + 8192);
            }
#pragma unroll
            for (int nt = 0; nt < 4; nt++) {
                int row = warpP * 32 + nt * 8 + lane8;
                uint32_t bd = stb + 16384 + row * 64 + ((((s << 1) | g1) ^ ((row >> 1) & 3)) << 4);
                LDSM2(bh[nt], bd);
                LDSM2(bl[nt], bd + 8192);
            }
#pragma unroll
            for (int mt = 0; mt < 4; mt++)
#pragma unroll
                for (int nt = 0; nt < 4; nt++) {
                    mma_bf16(acc[mt][nt], ah[mt], bh[nt]);
                    mma_bf16(acc[mt][nt], al_[mt], bh[nt]);
                    mma_bf16(acc[mt][nt], ah[mt], bl[nt]);
                }
        }
    }

#pragma unroll
    for (int mt = 0; mt < 4; mt++) {
#pragma unroll
        for (int nt = 0; nt < 4; nt++) {
            int o = oc + warpO * 64 + mt * 16 + (lane >> 2);
            int p = pc + warpP * 32 + nt * 8 + 2 * (lane & 3);
#pragma unroll
            for (int half = 0; half < 2; half++) {
                int oo = o + half * 8;
                float bv = bias ? bias[oo] : 0.f;
                float v0 = acc[mt][nt][half * 2 + 0] + bv;
                float v1 = acc[mt][nt][half * 2 + 1] + bv;
                if (addp) {
                    const float2 ad = *(const float2*)&addp[(size_t)oo * as + p];
                    v0 += ad.x; v1 += ad.y;
                }
                if (relu) { v0 = fmaxf(v0, 0.f); v1 = fmaxf(v1, 0.f); }
                if (out) {
                    float2 st = {v0, v1};
                    *(float2*)&out[(size_t)oo * os + outOff + p] = st;
                }
                if (oTh) {
                    __nv_bfloat16 h0 = __float2bfloat16_rn(v0);
                    __nv_bfloat16 h1 = __float2bfloat16_rn(v1);
                    oTh[(size_t)(outOff + p) * ots + oo] = h0;
                    oTh[(size_t)(outOff + p + 1) * ots + oo] = h1;
                    oTl[(size_t)(outOff + p) * ots + oo] =
                        __float2bfloat16_rn(v0 - __bfloat162float(h0));
                    oTl[(size_t)(outOff + p + 1) * ots + oo] =
                        __float2bfloat16_rn(v1 - __bfloat162float(h1));
                }
            }
        }
    }
}

// ---------------------------------------------------------------------------
// transpose+split / weight split (unchanged)
// ---------------------------------------------------------------------------
__global__ void t_split_k(const float* __restrict__ X, int P,
                          __nv_bfloat16* __restrict__ Th,
                          __nv_bfloat16* __restrict__ Tl, int C)
{
    __shared__ float s[32][33];
    int pb = blockIdx.x * 32, cb = blockIdx.y * 32;
    int tx = threadIdx.x, ty = threadIdx.y;
#pragma unroll
    for (int i = 0; i < 4; i++)
        s[ty + i * 8][tx] = X[(size_t)(cb + ty + i * 8) * P + pb + tx];
    __syncthreads();
#pragma unroll
    for (int i = 0; i < 4; i++) {
        int p = pb + ty + i * 8;
        int c = cb + tx;
        float v = s[tx][ty + i * 8];
        __nv_bfloat16 h = __float2bfloat16_rn(v);
        Th[(size_t)p * C + c] = h;
        Tl[(size_t)p * C + c] = __float2bfloat16_rn(v - __bfloat162float(h));
    }
}

struct WSplitArgs {
    const float* src[11];
    int n[11];
    int off[11];
    __nv_bfloat16* hi;
    __nv_bfloat16* lo;
};
__global__ void w_split_k(WSplitArgs a)
{
    int which = blockIdx.y;
    int i = blockIdx.x * 256 + threadIdx.x;
    if (i >= a.n[which]) return;
    float v = a.src[which][i];
    __nv_bfloat16 h = __float2bfloat16_rn(v);
    a.hi[a.off[which] + i] = h;
    a.lo[a.off[which] + i] = __float2bfloat16_rn(v - __bfloat162float(h));
}

// ---------------------------------------------------------------------------
// Fuser attention (R11)
// ---------------------------------------------------------------------------
__global__ __launch_bounds__(64) void attn_fus_k(
    const float* __restrict__ qF, const float* __restrict__ kF,
    const float* __restrict__ vF, float* __restrict__ msg)
{
    __shared__ float ks[4 * 1032];
    __shared__ float vs[4 * 1032];
    int tid = threadIdx.x;
    int h = blockIdx.y;
    int bz = blockIdx.z;
    int sub = tid >> 4, t = tid & 15;
    int qpos = bz * 64 + tid;
#pragma unroll 8
    for (int hd = 0; hd < 64; hd++) {
        ks[sub * 1032 + hd * 16 + t] = kF[(hd * 4 + h) * P_TRK + qpos];
        vs[sub * 1032 + hd * 16 + t] = vF[(hd * 4 + h) * P_TRK + qpos];
    }
    float qr[64];
#pragma unroll
    for (int hd = 0; hd < 64; hd++)
        qr[hd] = qF[(hd * 4 + h) * P_TRK + qpos];
    __syncthreads();
    float mx = -1e30f, sm = 0.f;
    float acc[64];
#pragma unroll
    for (int hd = 0; hd < 64; hd++) acc[hd] = 0.f;
    const float* kb = ks + sub * 1032;
    const float* vb = vs + sub * 1032;
    for (int ml = 0; ml < 16; ml++) {
        float s0 = 0, s1 = 0, s2 = 0, s3 = 0;
#pragma unroll
        for (int hd = 0; hd < 64; hd += 4) {
            s0 += qr[hd] * kb[hd * 16 + ml];
            s1 += qr[hd + 1] * kb[(hd + 1) * 16 + ml];
            s2 += qr[hd + 2] * kb[(hd + 2) * 16 + ml];
            s3 += qr[hd + 3] * kb[(hd + 3) * 16 + ml];
        }
        float s = ((s0 + s1) + (s2 + s3)) * 0.125f;
        float p;
        if (s > mx) {
            float c = __expf(mx - s);
            sm *= c;
#pragma unroll
            for (int hd = 0; hd < 64; hd++) acc[hd] *= c;
            mx = s; p = 1.f;
        } else p = __expf(s - mx);
        sm += p;
#pragma unroll
        for (int hd = 0; hd < 64; hd++) acc[hd] += p * vb[hd * 16 + ml];
    }
    float inv = 1.f / sm;
#pragma unroll
    for (int hd = 0; hd < 64; hd++)
        msg[(hd * 4 + h) * P_TRK + qpos] = acc[hd] * inv;
}

// ---------------------------------------------------------------------------
// GNN attention split-K partials (R11)
// ---------------------------------------------------------------------------
__global__ __launch_bounds__(64) void attn_part_k(
    const float* __restrict__ QKV, int cross,
    float* __restrict__ Pm, float* __restrict__ Ps, float* __restrict__ Pacc)
{
    __shared__ float ks[64][64];
    __shared__ float vs[64][64];
    int tid = threadIdx.x;
    int h = blockIdx.y;
    int bz = blockIdx.z >> 2, chunk = blockIdx.z & 3;
    int bx = blockIdx.x;
    int qbase, kbase, nk;
    if (bx < 4) {
        qbase = bz * 256 + bx * 64;
        if (cross) { kbase = 1024 + bz * 1024; nk = 1024; }
        else       { kbase = bz * 256;        nk = 256; }
    } else {
        qbase = 1024 + bz * 1024 + (bx - 4) * 64;
        if (cross) { kbase = bz * 256;        nk = 256; }
        else       { kbase = 1024 + bz * 1024; nk = 1024; }
    }
    int nkc = nk >> 2;
    int kstart = kbase + chunk * nkc;
    const float* kF = QKV + 256 * P_TD;
    const float* vF = QKV + 512 * P_TD;
    int qpos = qbase + tid;
    float qr[64];
#pragma unroll
    for (int hd = 0; hd < 64; hd++)
        qr[hd] = QKV[(hd * 4 + h) * P_TD + qpos];
    float mx = -1e30f, sm = 0.f;
    float acc[64];
#pragma unroll
    for (int hd = 0; hd < 64; hd++) acc[hd] = 0.f;

    for (int kt = 0; kt < nkc; kt += 64) {
        int kpos = kstart + kt + tid;
#pragma unroll
        for (int hd = 0; hd < 64; hd++) {
            ks[hd][tid] = kF[(hd * 4 + h) * P_TD + kpos];
            vs[hd][tid] = vF[(hd * 4 + h) * P_TD + kpos];
        }
        __syncthreads();
        for (int ml = 0; ml < 64; ml++) {
            float s0 = 0, s1 = 0, s2 = 0, s3 = 0;
#pragma unroll
            for (int hd = 0; hd < 64; hd += 4) {
                s0 += qr[hd] * ks[hd][ml];
                s1 += qr[hd + 1] * ks[hd + 1][ml];
                s2 += qr[hd + 2] * ks[hd + 2][ml];
                s3 += qr[hd + 3] * ks[hd + 3][ml];
            }
            float s = ((s0 + s1) + (s2 + s3)) * 0.125f;
            float p;
            if (s > mx) {
                float c = __expf(mx - s);
                sm *= c;
#pragma unroll
                for (int hd = 0; hd < 64; hd++) acc[hd] *= c;
                mx = s; p = 1.f;
            } else p = __expf(s - mx);
            sm += p;
#pragma unroll
            for (int hd = 0; hd < 64; hd++) acc[hd] += p * vs[hd][ml];
        }
        __syncthreads();
    }
    int slot = (qpos * 4 + h) * 4 + chunk;
    Pm[slot] = mx;
    Ps[slot] = sm;
    float* pa = Pacc + (size_t)slot * 64;
#pragma unroll
    for (int hd = 0; hd < 64; hd += 4)
        *(float4*)(pa + hd) = make_float4(acc[hd], acc[hd + 1], acc[hd + 2], acc[hd + 3]);
}

// ---------------------------------------------------------------------------
// Combine v2: merge 4 chunks, write transposed bf16 hi/lo msg directly.
// ---------------------------------------------------------------------------
__global__ __launch_bounds__(256) void attn_comb2_k(
    const float* __restrict__ Pm, const float* __restrict__ Ps,
    const float* __restrict__ Pacc,
    __nv_bfloat16* __restrict__ Th, __nv_bfloat16* __restrict__ Tl)
{
    extern __shared__ float srow[];   // [64][260]
    int tid = threadIdx.x;
    int ql = tid >> 2, h = tid & 3;
    int qpos = blockIdx.x * 64 + ql;
    int base = (qpos * 4 + h) * 4;
    float m0 = Pm[base], m1 = Pm[base + 1], m2 = Pm[base + 2], m3 = Pm[base + 3];
    float M = fmaxf(fmaxf(m0, m1), fmaxf(m2, m3));
    float e0 = __expf(m0 - M), e1 = __expf(m1 - M);
    float e2 = __expf(m2 - M), e3 = __expf(m3 - M);
    float S = Ps[base] * e0 + Ps[base + 1] * e1 + Ps[base + 2] * e2 + Ps[base + 3] * e3;
    float inv = 1.f / S;
    e0 *= inv; e1 *= inv; e2 *= inv; e3 *= inv;
    const float* a0 = Pacc + (size_t)(base + 0) * 64;
    const float* a1 = Pacc + (size_t)(base + 1) * 64;
    const float* a2 = Pacc + (size_t)(base + 2) * 64;
    const float* a3 = Pacc + (size_t)(base + 3) * 64;
    float* row = srow + ql * 260;
#pragma unroll 8
    for (int hd = 0; hd < 64; hd++)
        row[hd * 4 + h] = a0[hd] * e0 + a1[hd] * e1 + a2[hd] * e2 + a3[hd] * e3;
    __syncthreads();
    uint32_t* TH32 = (uint32_t*)Th;
    uint32_t* TL32 = (uint32_t*)Tl;
    int qbase = blockIdx.x * 64;
#pragma unroll
    for (int it = 0; it < 32; it++) {
        int i = it * 256 + tid;
        int r = i >> 7, cp = i & 127;
        float v0 = srow[r * 260 + cp * 2];
        float v1 = srow[r * 260 + cp * 2 + 1];
        __nv_bfloat162 hp = __floats2bfloat162_rn(v0, v1);
        __nv_bfloat162 lp = __floats2bfloat162_rn(v0 - __bfloat162float(hp.x),
                                                  v1 - __bfloat162float(hp.y));
        size_t o = (size_t)(qbase + r) * 128 + cp;
        TH32[o] = *(uint32_t*)&hp;
        TL32[o] = *(uint32_t*)&lp;
    }
}

// ---------------------------------------------------------------------------
// Gathers / PEs / pool
// ---------------------------------------------------------------------------
__global__ void gather_trk(const float* __restrict__ tracks, float* __restrict__ o)
{
    int idx = blockIdx.x * 256 + threadIdx.x;
    if (idx >= 256 * P_TRK) return;
    int c = idx >> 14, p = idx & 16383;
    int bi = p >> 4, t = p & 15;
    o[idx] = tracks[bi * 4112 + (c + 1) * 16 + t];
}
__global__ void gather_det(const float* __restrict__ det, float* __restrict__ o)
{
    int idx = blockIdx.x * 256 + threadIdx.x;
    if (idx >= 256 * P_DET) return;
    int c = idx >> 12, p = idx & 4095;
    int b = p >> 10, m = p & 1023;
    o[idx] = det[b * 263168 + (c + 1) * 1024 + m];
}
__global__ void pe_trk_k(const float* __restrict__ tracks, float* __restrict__ pe)
{
    int idx = blockIdx.x * 256 + threadIdx.x;
    if (idx >= 256 * P_TRK) return;
    int c = idx >> 14, p = idx & 16383;
    int bi = p >> 4, t = p & 15;
    float pos = tracks[bi * 4112 + t];
    float dv = expf((float)(c & ~1) * (-9.210340371976184f / 256.f));
    float ang = pos * dv;
    pe[idx] = (c & 1) ? cosf(ang) : sinf(ang);
}
__global__ void pe_det_k(const float* __restrict__ det, float* __restrict__ pe)
{
    int idx = blockIdx.x * 256 + threadIdx.x;
    if (idx >= 256 * P_DET) return;
    int c = idx >> 12, p = idx & 4095;
    int b = p >> 10, m = p & 1023;
    float pos = det[b * 263168 + m];
    float dv = expf((float)(c & ~1) * (-9.210340371976184f / 256.f));
    float ang = pos * dv;
    pe[idx] = (c & 1) ? cosf(ang) : sinf(ang);
}
__global__ void pool_k(const float* __restrict__ x, float* __restrict__ td)
{
    int idx = blockIdx.x * 256 + threadIdx.x;
    if (idx >= 256 * P_TR) return;
    int c = idx >> 10, bi = idx & 1023;
    const float* p = x + c * P_TRK + bi * 16;
    float s = 0.f;
#pragma unroll
    for (int t = 0; t < 16; t++) s += p[t];
    td[c * P_TD + bi] = s * 0.0625f;
}

// ---------------------------------------------------------------------------
// scores / bins / log-domain Sinkhorn (R11 proven version)
// ---------------------------------------------------------------------------
__global__ __launch_bounds__(256) void scores_k(
    const float* __restrict__ M01, float* __restrict__ Z0)
{
    __shared__ float As[16][64];
    __shared__ float Bs[16][64];
    int tid = threadIdx.x, tx = tid & 15, ty = tid >> 4;
    int b = blockIdx.z;
    int nc = blockIdx.y * 64, mc = blockIdx.x * 64;
    float acc[4][4] = {};
    for (int kc = 0; kc < 256; kc += 16) {
#pragma unroll
        for (int r = 0; r < 4; r++) {
            int e = tid + r * 256;
            int kl = e >> 6, nl = e & 63;
            As[kl][nl] = M01[(kc + kl) * P_TD + b * 256 + nc + nl];
        }
#pragma unroll
        for (int r = 0; r < 4; r++) {
            int e = tid + r * 256;
            int kl = e >> 6, ml = e & 63;
            Bs[kl][ml] = M01[(kc + kl) * P_TD + 1024 + b * 1024 + mc + ml];
        }
        __syncthreads();
#pragma unroll
        for (int kk = 0; kk < 16; kk++) {
            float a[4], bb[4];
#pragma unroll
            for (int i = 0; i < 4; i++) a[i] = As[kk][ty * 4 + i];
#pragma unroll
            for (int j = 0; j < 4; j++) bb[j] = Bs[kk][tx * 4 + j];
#pragma unroll
            for (int i = 0; i < 4; i++)
#pragma unroll
                for (int j = 0; j < 4; j++) acc[i][j] += a[i] * bb[j];
        }
        __syncthreads();
    }
#pragma unroll
    for (int i = 0; i < 4; i++) {
        int n = nc + ty * 4 + i;
#pragma unroll
        for (int j = 0; j < 4; j++) {
            int m = mc + tx * 4 + j;
            Z0[b * ZROW + n * 1025 + m] = acc[i][j] * 0.0625f;
        }
    }
}

__global__ void fill_bins(float* __restrict__ Z0, const float* __restrict__ alpha_p)
{
    float a = *alpha_p;
    int idx = blockIdx.x * 256 + threadIdx.x;
    if (idx < 1024) {
        int b = idx >> 8, i = idx & 255;
        Z0[b * ZROW + i * 1025 + 1024] = a;
    }
    int idx2 = idx - 1024;
    if (idx2 >= 0 && idx2 < 4100) {
        int b = idx2 / 1025, j = idx2 % 1025;
        Z0[b * ZROW + 256 * 1025 + j] = a;
    }
}

__global__ void zero_k(float* p, int n)
{
    int i = blockIdx.x * 256 + threadIdx.x;
    if (i < n) p[i] = 0.f;
}

__device__ __forceinline__ void lse_merge(float& m, float& s, float om, float os)
{
    float M = fmaxf(m, om);
    s = s * __expf(m - M) + os * __expf(om - M);
    m = M;
}

__device__ __forceinline__ void grid_bar(unsigned* cnt, unsigned target)
{
    __syncthreads();
    if (threadIdx.x == 0) {
        __threadfence();
        atomicAdd(cnt, 1u);
        volatile unsigned* vc = cnt;
        while (*vc < target * (unsigned)NBLK_SINK) {}
        __threadfence();
    }
    __syncthreads();
}

__global__ __launch_bounds__(256) void sink_fused_k(
    const float* __restrict__ Z0, float* __restrict__ u, float* __restrict__ v,
    unsigned* __restrict__ cnt)
{
    __shared__ float smm[8], sss[8];
    __shared__ float smm2[8][33], sss2[8][33];
    int tid = threadIdx.x;
    int w = tid >> 5, l = tid & 31;
    unsigned phase = 0;

    for (int it = 0; it < 100; it++) {
        for (int row = blockIdx.x; row < 1028; row += NBLK_SINK) {
            int b = row / 257, i = row % 257;
            const float* zr = Z0 + b * ZROW + i * 1025;
            const float* vb = v + b * 1025;
            float m = -1e30f, s = 0.f;
            for (int j = tid; j < 1025; j += 256) {
                float z = zr[j] + vb[j];
                if (z > m) { s = s * __expf(m - z) + 1.f; m = z; }
                else s += __expf(z - m);
            }
            for (int off = 16; off; off >>= 1) {
                float om = __shfl_down_sync(0xffffffffu, m, off);
                float os = __shfl_down_sync(0xffffffffu, s, off);
                lse_merge(m, s, om, os);
            }
            if (l == 0) { smm[w] = m; sss[w] = s; }
            __syncthreads();
            if (tid == 0) {
                m = smm[0]; s = sss[0];
                for (int k = 1; k < 8; k++) lse_merge(m, s, smm[k], sss[k]);
                float logmu = (i < 256) ? NORM_C : (NORM_C + LOG1024);
                u[row] = logmu - (m + __logf(s));
            }
            __syncthreads();
        }
        phase++; grid_bar(cnt, phase);

        for (int task = blockIdx.x; task < 132; task += NBLK_SINK) {
            int b = task / 33, jt = task % 33;
            int j = jt * 32 + l;
            float m = -1e30f, s = 0.f;
            if (j < 1025) {
                const float* zb = Z0 + b * ZROW;
                const float* ub = u + b * 257;
                for (int i = w; i < 257; i += 8) {
                    float z = zb[i * 1025 + j] + ub[i];
                    if (z > m) { s = s * __expf(m - z) + 1.f; m = z; }
                    else s += __expf(z - m);
                }
            }
            smm2[w][l] = m; sss2[w][l] = s;
            __syncthreads();
            if (w == 0 && j < 1025) {
                m = smm2[0][l]; s = sss2[0][l];
                for (int k = 1; k < 8; k++) lse_merge(m, s, smm2[k][l], sss2[k][l]);
                float lognu = (j < 1024) ? NORM_C : (NORM_C + LOG256);
                v[b * 1025 + j] = lognu - (m + __logf(s));
            }
            __syncthreads();
        }
        phase++; grid_bar(cnt, phase);
    }
}

__global__ void sink_out(const float* __restrict__ Z0, const float* __restrict__ u,
                         const float* __restrict__ v, float* __restrict__ out)
{
    int idx = blockIdx.x * 256 + threadIdx.x;
    if (idx >= 4 * ZROW) return;
    int b = idx / ZROW;
    int r = idx - b * ZROW;
    int i = r / 1025, j = r - i * 1025;
    out[idx] = Z0[idx] + u[b * 257 + i] + v[b * 1025 + j] - NORM_C;
}

// ---------------------------------------------------------------------------
// Host orchestration
// ---------------------------------------------------------------------------
typedef __nv_bfloat16 bf;

static void gemmN(const bf* Wh, const bf* Wl, const float* bias,
                  const bf* Xh, const bf* Xl, int xs,
                  const bf* X2h, const bf* X2l, int x2s,
                  const float* addp, int as, float* out, int os,
                  bf* oTh, bf* oTl, int ots,
                  int outOff, int O, int I, int Pcols, int relu)
{
    dim3 g(Pcols / 128, O / 128);
    gemm_bf2_k<<<g, 256, 98304>>>(Wh, Wl, bias, Xh, Xl, X2h, X2l, xs, x2s,
                                  addp, as, out, os, oTh, oTl, ots, outOff, I, relu);
}
static void tsplit(const float* X, int C, int P, bf* Th, bf* Tl)
{
    dim3 g(P / 32, C / 32);
    t_split_k<<<g, dim3(32, 8)>>>(X, P, Th, Tl, C);
}

#define OW_ENC1   0
#define OW_ENC2   65536
#define OW_FPW    131072
#define OW_FMW    917504
#define OW_FM1    1179648
#define OW_FM2    2228224
#define OW_GPW    2752512
#define OW_GMW    5111808
#define OW_GM1    5898240
#define OW_GM2    9043968
#define OW_FIN    10616832

extern "C" void kernel_launch(void* const* d_in, const int* in_sizes, int n_in,
                              void* d_out, int out_size)
{
    const float* detections = (const float*)d_in[0];
    const float* tracks     = (const float*)d_in[1];
    const float* enc_w1 = (const float*)d_in[2];
    const float* enc_b1 = (const float*)d_in[3];
    const float* enc_w2 = (const float*)d_in[4];
    const float* enc_b2 = (const float*)d_in[5];
    const float* fus_pw  = (const float*)d_in[6];
    const float* fus_pb  = (const float*)d_in[7];
    const float* fus_mw  = (const float*)d_in[8];
    const float* fus_mb  = (const float*)d_in[9];
    const float* fus_m1w = (const float*)d_in[10];
    const float* fus_m1b = (const float*)d_in[11];
    const float* fus_m2w = (const float*)d_in[12];
    const float* fus_m2b = (const float*)d_in[13];
    const float* gnn_pw  = (const float*)d_in[14];
    const float* gnn_pb  = (const float*)d_in[15];
    const float* gnn_mw  = (const float*)d_in[16];
    const float* gnn_mb  = (const float*)d_in[17];
    const float* gnn_m1w = (const float*)d_in[18];
    const float* gnn_m1b = (const float*)d_in[19];
    const float* gnn_m2w = (const float*)d_in[20];
    const float* gnn_m2b = (const float*)d_in[21];
    const float* final_w = (const float*)d_in[22];
    const float* final_b = (const float*)d_in[23];
    const float* bin_score = (const float*)d_in[24];
    float* out = (float*)d_out;

    cudaFuncSetAttribute(gemm_bf2_k, cudaFuncAttributeMaxDynamicSharedMemorySize, 98304);
    cudaFuncSetAttribute(attn_comb2_k, cudaFuncAttributeMaxDynamicSharedMemorySize, 66560);

    float* pool = nullptr;
    cudaGetSymbolAddress((void**)&pool, g_pool);
    size_t off = 0;
    auto carve = [&](size_t n) { float* p = pool + off; off += n; return p; };
    bf* WH       = (bf*)carve(5341184);
    bf* WL       = (bf*)carve(5341184);
    float* TRKIN = carve(4194304);
    float* DETIN = carve(1048576);
    float* TRKPE = carve(4194304);
    float* DETPE = carve(1048576);
    bf* TRKINT_H = (bf*)carve(2097152);
    bf* TRKINT_L = (bf*)carve(2097152);
    bf* DETINT_H = (bf*)carve(524288);
    bf* DETINT_L = (bf*)carve(524288);
    float* QKV   = carve(12582912);
    float* MSG   = carve(4194304);
    bf* MSGT_H   = (bf*)carve(2097152);
    bf* MSGT_L   = (bf*)carve(2097152);
    bf* MSG2T_H  = (bf*)carve(2097152);
    bf* MSG2T_L  = (bf*)carve(2097152);
    bf* TMP1T_H  = (bf*)carve(4194304);
    bf* TMP1T_L  = (bf*)carve(4194304);
    float* XA    = carve(4194304);
    float* XB    = carve(4194304);
    bf* XAT_H    = (bf*)carve(2097152);
    bf* XAT_L    = (bf*)carve(2097152);
    bf* XBT_H    = (bf*)carve(2097152);
    bf* XBT_L    = (bf*)carve(2097152);
    float* TDA   = carve(1310720);
    float* TDB   = carve(1310720);
    bf* TDAT_H   = (bf*)carve(655360);
    bf* TDAT_L   = (bf*)carve(655360);
    bf* TDBT_H   = (bf*)carve(655360);
    bf* TDBT_L   = (bf*)carve(655360);
    float* M01   = carve(1310720);
    float* Z0    = carve(1053700);
    float* U     = carve(1028);
    float* V     = carve(4100);
    float* CNT   = carve(4);
    float* PM    = carve(81920);
    float* PS    = carve(81920);
    float* PACC  = carve(5242880);

    WSplitArgs wa;
    const float* srcs[11] = {enc_w1, enc_w2, fus_pw, fus_mw, fus_m1w, fus_m2w,
                             gnn_pw, gnn_mw, gnn_m1w, gnn_m2w, final_w};
    int ns[11] = {65536, 65536, 786432, 262144, 1048576, 524288,
                  2359296, 786432, 3145728, 1572864, 65536};
    int ofs[11] = {OW_ENC1, OW_ENC2, OW_FPW, OW_FMW, OW_FM1, OW_FM2,
                   OW_GPW, OW_GMW, OW_GM1, OW_GM2, OW_FIN};
    for (int i = 0; i < 11; i++) { wa.src[i] = srcs[i]; wa.n[i] = ns[i]; wa.off[i] = ofs[i]; }
    wa.hi = WH; wa.lo = WL;
    w_split_k<<<dim3(12288, 11), 256>>>(wa);

    gather_trk<<<16384, 256>>>(tracks, TRKIN);
    gather_det<<<4096, 256>>>(detections, DETIN);
    tsplit(TRKIN, 256, P_TRK, TRKINT_H, TRKINT_L);
    gemmN(WH + OW_ENC1, WL + OW_ENC1, enc_b1, TRKINT_H, TRKINT_L, 256,
          nullptr, nullptr, 0, nullptr, 0, nullptr, 0,
          TMP1T_H, TMP1T_L, 256, 0, 256, 256, P_TRK, 1);
    tsplit(DETIN, 256, P_DET, DETINT_H, DETINT_L);
    pe_trk_k<<<16384, 256>>>(tracks, TRKPE);
    pe_det_k<<<4096, 256>>>(detections, DETPE);
    gemmN(WH + OW_ENC2, WL + OW_ENC2, enc_b2, TMP1T_H, TMP1T_L, 256,
          nullptr, nullptr, 0, TRKPE, P_TRK, XA, P_TRK,
          XAT_H, XAT_L, 256, 0, 256, 256, P_TRK, 0);
    gemmN(WH + OW_ENC1, WL + OW_ENC1, enc_b1, DETINT_H, DETINT_L, 256,
          nullptr, nullptr, 0, nullptr, 0, nullptr, 0,
          TMP1T_H, TMP1T_L, 256, 0, 256, 256, P_DET, 1);
    gemmN(WH + OW_ENC2, WL + OW_ENC2, enc_b2, TMP1T_H, TMP1T_L, 256,
          nullptr, nullptr, 0, DETPE, P_DET, TDA, P_TD,
          nullptr, nullptr, 0, 1024, 256, 256, P_DET, 0);

    float* x = XA; float* xo = XB;
    bf *xTh = XAT_H, *xTl = XAT_L, *xoTh = XBT_H, *xoTl = XBT_L;
    for (int l = 0; l < 4; l++) {
        gemmN(WH + OW_FPW + l * 196608, WL + OW_FPW + l * 196608, fus_pb + l * 768,
              xTh, xTl, 256, nullptr, nullptr, 0, nullptr, 0,
              QKV, P_TRK, nullptr, nullptr, 0, 0, 768, 256, P_TRK, 0);
        attn_fus_k<<<dim3(1, 4, 256), 64>>>(QKV, QKV + 256 * P_TRK, QKV + 512 * P_TRK, MSG);
        tsplit(MSG, 256, P_TRK, MSGT_H, MSGT_L);
        gemmN(WH + OW_FMW + l * 65536, WL + OW_FMW + l * 65536, fus_mb + l * 256,
              MSGT_H, MSGT_L, 256, nullptr, nullptr, 0, nullptr, 0,
              nullptr, 0, MSG2T_H, MSG2T_L, 256, 0, 256, 256, P_TRK, 0);
        gemmN(WH + OW_FM1 + l * 262144, WL + OW_FM1 + l * 262144, fus_m1b + l * 512,
              xTh, xTl, 256, MSG2T_H, MSG2T_L, 256, nullptr, 0,
              nullptr, 0, TMP1T_H, TMP1T_L, 512, 0, 512, 512, P_TRK, 1);
        gemmN(WH + OW_FM2 + l * 131072, WL + OW_FM2 + l * 131072, fus_m2b + l * 256,
              TMP1T_H, TMP1T_L, 512, nullptr, nullptr, 0, x, P_TRK,
              xo, P_TRK, xoTh, xoTl, 256, 0, 256, 512, P_TRK, 0);
        float* t = x; x = xo; xo = t;
        bf* th = xTh; xTh = xoTh; xoTh = th;
        bf* tl = xTl; xTl = xoTl; xoTl = tl;
    }
    pool_k<<<1024, 256>>>(x, TDA);
    tsplit(TDA, 256, P_TD, TDAT_H, TDAT_L);

    float* td = TDA; float* tdo = TDB;
    bf *tdTh = TDAT_H, *tdTl = TDAT_L, *tdoTh = TDBT_H, *tdoTl = TDBT_L;
    for (int l = 0; l < 12; l++) {
        int cross = l & 1;
        gemmN(WH + OW_GPW + l * 196608, WL + OW_GPW + l * 196608, gnn_pb + l * 768,
              tdTh, tdTl, 256, nullptr, nullptr, 0, nullptr, 0,
              QKV, P_TD, nullptr, nullptr, 0, 0, 768, 256, P_TD, 0);
        attn_part_k<<<dim3(20, 4, 16), 64>>>(QKV, cross, PM, PS, PACC);
        attn_comb2_k<<<80, 256, 66560>>>(PM, PS, PACC, MSGT_H, MSGT_L);
        gemmN(WH + OW_GMW + l * 65536, WL + OW_GMW + l * 65536, gnn_mb + l * 256,
              MSGT_H, MSGT_L, 256, nullptr, nullptr, 0, nullptr, 0,
              nullptr, 0, MSG2T_H, MSG2T_L, 256, 0, 256, 256, P_TD, 0);
        gemmN(WH + OW_GM1 + l * 262144, WL + OW_GM1 + l * 262144, gnn_m1b + l * 512,
              tdTh, tdTl, 256, MSG2T_H, MSG2T_L, 256, nullptr, 0,
              nullptr, 0, TMP1T_H, TMP1T_L, 512, 0, 512, 512, P_TD, 1);
        gemmN(WH + OW_GM2 + l * 131072, WL + OW_GM2 + l * 131072, gnn_m2b + l * 256,
              TMP1T_H, TMP1T_L, 512, nullptr, nullptr, 0, td, P_TD,
              tdo, P_TD, tdoTh, tdoTl, 256, 0, 256, 512, P_TD, 0);
        float* t = td; td = tdo; tdo = t;
        bf* th = tdTh; tdTh = tdoTh; tdoTh = th;
        bf* tl = tdTl; tdTl = tdoTl; tdoTl = tl;
    }

    gemmN(WH + OW_FIN, WL + OW_FIN, final_b, tdTh, tdTl, 256,
          nullptr, nullptr, 0, nullptr, 0, M01, P_TD,
          nullptr, nullptr, 0, 0, 256, 256, P_TD, 0);
    scores_k<<<dim3(16, 4, 4), 256>>>(M01, Z0);
    fill_bins<<<21, 256>>>(Z0, bin_score);
    zero_k<<<21, 256>>>(U, 5129);

    sink_fused_k<<<NBLK_SINK, 256>>>(Z0, U, V, (unsigned*)CNT);
    sink_out<<<(4 * ZROW + 255) / 256, 256>>>(Z0, U, V, out);
    (void)in_sizes; (void)n_in; (void)out_size;
}

// round 17
// speedup vs baseline: 1.0565x; 1.0565x over previous
#include <cuda_runtime.h>
#include <cuda_bf16.h>
#include <math.h>
#include <stdint.h>

// B=4, N_TR=256, M_DET=1024, T=16, D=256, H=4, HD=64, N_FUSER=4, N_GNN=12, ITERS=100
#define P_TRK 16384
#define P_DET 4096
#define P_TR  1024
#define P_TD  5120
#define ZROW  263425
#define NORM_C  (-7.1546153569136625f)
#define LOG1024 6.931471805599453f
#define LOG256  5.545177444479562f
#define NBLK_SINK 148

__device__ float g_pool[100000000];

// ---------------------------------------------------------------------------
// mma / ldmatrix / cp.async wrappers
// ---------------------------------------------------------------------------
__device__ __forceinline__ void mma_bf16(float* c, const uint32_t* a, const uint32_t* b)
{
    asm volatile(
        "mma.sync.aligned.m16n8k16.row.col.f32.bf16.bf16.f32 "
        "{%0,%1,%2,%3}, {%4,%5,%6,%7}, {%8,%9}, {%0,%1,%2,%3};"
        : "+f"(c[0]), "+f"(c[1]), "+f"(c[2]), "+f"(c[3])
        : "r"(a[0]), "r"(a[1]), "r"(a[2]), "r"(a[3]), "r"(b[0]), "r"(b[1]));
}
#define LDSM4(r, a) \
    asm volatile("ldmatrix.sync.aligned.m8n8.x4.shared.b16 {%0,%1,%2,%3}, [%4];" \
                 : "=r"((r)[0]), "=r"((r)[1]), "=r"((r)[2]), "=r"((r)[3]) : "r"(a))
#define LDSM2(r, a) \
    asm volatile("ldmatrix.sync.aligned.m8n8.x2.shared.b16 {%0,%1}, [%2];" \
                 : "=r"((r)[0]), "=r"((r)[1]) : "r"(a))
__device__ __forceinline__ void cpa16(uint32_t dst, const void* src)
{
    asm volatile("cp.async.ca.shared.global [%0], [%1], 16;" :: "r"(dst), "l"(src));
}

// ---------------------------------------------------------------------------
// bf16x2 tensor GEMM (R11 body, 1 CTA/SM)
// ---------------------------------------------------------------------------
__global__ __launch_bounds__(256, 1) void gemm_bf2_k(
    const __nv_bfloat16* __restrict__ Whi, const __nv_bfloat16* __restrict__ Wlo,
    const float* __restrict__ bias,
    const __nv_bfloat16* __restrict__ Xh, const __nv_bfloat16* __restrict__ Xl,
    const __nv_bfloat16* __restrict__ X2h, const __nv_bfloat16* __restrict__ X2l,
    int xs, int x2s,
    const float* __restrict__ addp, int as,
    float* __restrict__ out, int os,
    __nv_bfloat16* __restrict__ oTh, __nv_bfloat16* __restrict__ oTl, int ots,
    int outOff, int I, int relu)
{
    extern __shared__ char sm[];
    uint32_t sb = (uint32_t)__cvta_generic_to_shared(sm);
    int tid = threadIdx.x, warp = tid >> 5, lane = tid & 31;
    int warpO = warp >> 2, warpP = warp & 3;
    int pc = blockIdx.x * 128, oc = blockIdx.y * 128;
    int lrow = tid >> 1, lhalf = tid & 1;
    int nch = I >> 5;

    auto issue = [&](int c, int st) {
        uint32_t stb = sb + st * 32768;
        int kc = c * 32;
        int sw = (lrow >> 1) & 3;
        uint32_t s0 = (uint32_t)(((lhalf * 2 + 0) ^ sw) << 4);
        uint32_t s1 = (uint32_t)(((lhalf * 2 + 1) ^ sw) << 4);
        {
            const __nv_bfloat16* sh = Whi + (size_t)(oc + lrow) * I + kc + lhalf * 16;
            const __nv_bfloat16* sl = Wlo + (size_t)(oc + lrow) * I + kc + lhalf * 16;
            uint32_t rb = stb + lrow * 64;
            cpa16(rb + s0, sh); cpa16(rb + s1, sh + 8);
            cpa16(rb + 8192 + s0, sl); cpa16(rb + 8192 + s1, sl + 8);
        }
        {
            const __nv_bfloat16 *sh, *sl;
            if (X2h != nullptr && kc >= 256) {
                sh = X2h + (size_t)(pc + lrow) * x2s + (kc - 256) + lhalf * 16;
                sl = X2l + (size_t)(pc + lrow) * x2s + (kc - 256) + lhalf * 16;
            } else {
                sh = Xh + (size_t)(pc + lrow) * xs + kc + lhalf * 16;
                sl = Xl + (size_t)(pc + lrow) * xs + kc + lhalf * 16;
            }
            uint32_t rb = stb + 16384 + lrow * 64;
            cpa16(rb + s0, sh); cpa16(rb + s1, sh + 8);
            cpa16(rb + 8192 + s0, sl); cpa16(rb + 8192 + s1, sl + 8);
        }
        asm volatile("cp.async.commit_group;" ::: "memory");
    };

    issue(0, 0);
    if (nch > 1) issue(1, 1);

    float acc[4][4][4];
#pragma unroll
    for (int mt = 0; mt < 4; mt++)
#pragma unroll
        for (int nt = 0; nt < 4; nt++)
#pragma unroll
            for (int i = 0; i < 4; i++) acc[mt][nt][i] = 0.f;

    int lane8 = lane & 7, g1 = (lane >> 3) & 1, g2 = lane >> 4;

    for (int c = 0; c < nch; c++) {
        if (c < nch - 1) asm volatile("cp.async.wait_group 1;" ::: "memory");
        else             asm volatile("cp.async.wait_group 0;" ::: "memory");
        __syncthreads();
        if (c + 2 < nch) issue(c + 2, (c + 2) % 3);
        uint32_t stb = sb + (c % 3) * 32768;
#pragma unroll
        for (int s = 0; s < 2; s++) {
            uint32_t ah[4][4], al_[4][4], bh[4][2], bl[4][2];
#pragma unroll
            for (int mt = 0; mt < 4; mt++) {
                int row = warpO * 64 + mt * 16 + lane8 + g1 * 8;
                uint32_t ad = stb + row * 64 + ((((s << 1) | g2) ^ ((row >> 1) & 3)) << 4);
                LDSM4(ah[mt], ad);
                LDSM4(al_[mt], ad + 8192);
            }
#pragma unroll
            for (int nt = 0; nt < 4; nt++) {
                int row = warpP * 32 + nt * 8 + lane8;
                uint32_t bd = stb + 16384 + row * 64 + ((((s << 1) | g1) ^ ((row >> 1) & 3)) << 4);
                LDSM2(bh[nt], bd);
                LDSM2(bl[nt], bd + 8192);
            }
#pragma unroll
            for (int mt = 0; mt < 4; mt++)
#pragma unroll
                for (int nt = 0; nt < 4; nt++) {
                    mma_bf16(acc[mt][nt], ah[mt], bh[nt]);
                    mma_bf16(acc[mt][nt], al_[mt], bh[nt]);
                    mma_bf16(acc[mt][nt], ah[mt], bl[nt]);
                }
        }
    }

#pragma unroll
    for (int mt = 0; mt < 4; mt++) {
#pragma unroll
        for (int nt = 0; nt < 4; nt++) {
            int o = oc + warpO * 64 + mt * 16 + (lane >> 2);
            int p = pc + warpP * 32 + nt * 8 + 2 * (lane & 3);
#pragma unroll
            for (int half = 0; half < 2; half++) {
                int oo = o + half * 8;
                float bv = bias ? bias[oo] : 0.f;
                float v0 = acc[mt][nt][half * 2 + 0] + bv;
                float v1 = acc[mt][nt][half * 2 + 1] + bv;
                if (addp) {
                    const float2 ad = *(const float2*)&addp[(size_t)oo * as + p];
                    v0 += ad.x; v1 += ad.y;
                }
                if (relu) { v0 = fmaxf(v0, 0.f); v1 = fmaxf(v1, 0.f); }
                if (out) {
                    float2 st = {v0, v1};
                    *(float2*)&out[(size_t)oo * os + outOff + p] = st;
                }
                if (oTh) {
                    __nv_bfloat16 h0 = __float2bfloat16_rn(v0);
                    __nv_bfloat16 h1 = __float2bfloat16_rn(v1);
                    oTh[(size_t)(outOff + p) * ots + oo] = h0;
                    oTh[(size_t)(outOff + p + 1) * ots + oo] = h1;
                    oTl[(size_t)(outOff + p) * ots + oo] =
                        __float2bfloat16_rn(v0 - __bfloat162float(h0));
                    oTl[(size_t)(outOff + p + 1) * ots + oo] =
                        __float2bfloat16_rn(v1 - __bfloat162float(h1));
                }
            }
        }
    }
}

// ---------------------------------------------------------------------------
// transpose+split / weight split (unchanged)
// ---------------------------------------------------------------------------
__global__ void t_split_k(const float* __restrict__ X, int P,
                          __nv_bfloat16* __restrict__ Th,
                          __nv_bfloat16* __restrict__ Tl, int C)
{
    __shared__ float s[32][33];
    int pb = blockIdx.x * 32, cb = blockIdx.y * 32;
    int tx = threadIdx.x, ty = threadIdx.y;
#pragma unroll
    for (int i = 0; i < 4; i++)
        s[ty + i * 8][tx] = X[(size_t)(cb + ty + i * 8) * P + pb + tx];
    __syncthreads();
#pragma unroll
    for (int i = 0; i < 4; i++) {
        int p = pb + ty + i * 8;
        int c = cb + tx;
        float v = s[tx][ty + i * 8];
        __nv_bfloat16 h = __float2bfloat16_rn(v);
        Th[(size_t)p * C + c] = h;
        Tl[(size_t)p * C + c] = __float2bfloat16_rn(v - __bfloat162float(h));
    }
}

struct WSplitArgs {
    const float* src[11];
    int n[11];
    int off[11];
    __nv_bfloat16* hi;
    __nv_bfloat16* lo;
};
__global__ void w_split_k(WSplitArgs a)
{
    int which = blockIdx.y;
    int i = blockIdx.x * 256 + threadIdx.x;
    if (i >= a.n[which]) return;
    float v = a.src[which][i];
    __nv_bfloat16 h = __float2bfloat16_rn(v);
    a.hi[a.off[which] + i] = h;
    a.lo[a.off[which] + i] = __float2bfloat16_rn(v - __bfloat162float(h));
}

// ---------------------------------------------------------------------------
// Fuser attention (R11)
// ---------------------------------------------------------------------------
__global__ __launch_bounds__(64) void attn_fus_k(
    const float* __restrict__ qF, const float* __restrict__ kF,
    const float* __restrict__ vF, float* __restrict__ msg)
{
    __shared__ float ks[4 * 1032];
    __shared__ float vs[4 * 1032];
    int tid = threadIdx.x;
    int h = blockIdx.y;
    int bz = blockIdx.z;
    int sub = tid >> 4, t = tid & 15;
    int qpos = bz * 64 + tid;
#pragma unroll 8
    for (int hd = 0; hd < 64; hd++) {
        ks[sub * 1032 + hd * 16 + t] = kF[(hd * 4 + h) * P_TRK + qpos];
        vs[sub * 1032 + hd * 16 + t] = vF[(hd * 4 + h) * P_TRK + qpos];
    }
    float qr[64];
#pragma unroll
    for (int hd = 0; hd < 64; hd++)
        qr[hd] = qF[(hd * 4 + h) * P_TRK + qpos];
    __syncthreads();
    float mx = -1e30f, sm = 0.f;
    float acc[64];
#pragma unroll
    for (int hd = 0; hd < 64; hd++) acc[hd] = 0.f;
    const float* kb = ks + sub * 1032;
    const float* vb = vs + sub * 1032;
    for (int ml = 0; ml < 16; ml++) {
        float s0 = 0, s1 = 0, s2 = 0, s3 = 0;
#pragma unroll
        for (int hd = 0; hd < 64; hd += 4) {
            s0 += qr[hd] * kb[hd * 16 + ml];
            s1 += qr[hd + 1] * kb[(hd + 1) * 16 + ml];
            s2 += qr[hd + 2] * kb[(hd + 2) * 16 + ml];
            s3 += qr[hd + 3] * kb[(hd + 3) * 16 + ml];
        }
        float s = ((s0 + s1) + (s2 + s3)) * 0.125f;
        float p;
        if (s > mx) {
            float c = __expf(mx - s);
            sm *= c;
#pragma unroll
            for (int hd = 0; hd < 64; hd++) acc[hd] *= c;
            mx = s; p = 1.f;
        } else p = __expf(s - mx);
        sm += p;
#pragma unroll
        for (int hd = 0; hd < 64; hd++) acc[hd] += p * vb[hd * 16 + ml];
    }
    float inv = 1.f / sm;
#pragma unroll
    for (int hd = 0; hd < 64; hd++)
        msg[(hd * 4 + h) * P_TRK + qpos] = acc[hd] * inv;
}

// ---------------------------------------------------------------------------
// GNN attention split-K partials (R11)
// ---------------------------------------------------------------------------
__global__ __launch_bounds__(64) void attn_part_k(
    const float* __restrict__ QKV, int cross,
    float* __restrict__ Pm, float* __restrict__ Ps, float* __restrict__ Pacc)
{
    __shared__ float ks[64][64];
    __shared__ float vs[64][64];
    int tid = threadIdx.x;
    int h = blockIdx.y;
    int bz = blockIdx.z >> 2, chunk = blockIdx.z & 3;
    int bx = blockIdx.x;
    int qbase, kbase, nk;
    if (bx < 4) {
        qbase = bz * 256 + bx * 64;
        if (cross) { kbase = 1024 + bz * 1024; nk = 1024; }
        else       { kbase = bz * 256;        nk = 256; }
    } else {
        qbase = 1024 + bz * 1024 + (bx - 4) * 64;
        if (cross) { kbase = bz * 256;        nk = 256; }
        else       { kbase = 1024 + bz * 1024; nk = 1024; }
    }
    int nkc = nk >> 2;
    int kstart = kbase + chunk * nkc;
    const float* kF = QKV + 256 * P_TD;
    const float* vF = QKV + 512 * P_TD;
    int qpos = qbase + tid;
    float qr[64];
#pragma unroll
    for (int hd = 0; hd < 64; hd++)
        qr[hd] = QKV[(hd * 4 + h) * P_TD + qpos];
    float mx = -1e30f, sm = 0.f;
    float acc[64];
#pragma unroll
    for (int hd = 0; hd < 64; hd++) acc[hd] = 0.f;

    for (int kt = 0; kt < nkc; kt += 64) {
        int kpos = kstart + kt + tid;
#pragma unroll
        for (int hd = 0; hd < 64; hd++) {
            ks[hd][tid] = kF[(hd * 4 + h) * P_TD + kpos];
            vs[hd][tid] = vF[(hd * 4 + h) * P_TD + kpos];
        }
        __syncthreads();
        for (int ml = 0; ml < 64; ml++) {
            float s0 = 0, s1 = 0, s2 = 0, s3 = 0;
#pragma unroll
            for (int hd = 0; hd < 64; hd += 4) {
                s0 += qr[hd] * ks[hd][ml];
                s1 += qr[hd + 1] * ks[hd + 1][ml];
                s2 += qr[hd + 2] * ks[hd + 2][ml];
                s3 += qr[hd + 3] * ks[hd + 3][ml];
            }
            float s = ((s0 + s1) + (s2 + s3)) * 0.125f;
            float p;
            if (s > mx) {
                float c = __expf(mx - s);
                sm *= c;
#pragma unroll
                for (int hd = 0; hd < 64; hd++) acc[hd] *= c;
                mx = s; p = 1.f;
            } else p = __expf(s - mx);
            sm += p;
#pragma unroll
            for (int hd = 0; hd < 64; hd++) acc[hd] += p * vs[hd][ml];
        }
        __syncthreads();
    }
    int slot = (qpos * 4 + h) * 4 + chunk;
    Pm[slot] = mx;
    Ps[slot] = sm;
    float* pa = Pacc + (size_t)slot * 64;
#pragma unroll
    for (int hd = 0; hd < 64; hd += 4)
        *(float4*)(pa + hd) = make_float4(acc[hd], acc[hd + 1], acc[hd + 2], acc[hd + 3]);
}

// ---------------------------------------------------------------------------
// Combine v3: coalesced merge of 4 chunks + direct transposed bf16 hi/lo out.
// grid 80 x 256 (8 warps). Block = 64 qpos x 4 h.
// smem: srow[64][268] (layout [ql][h*67+hd]) + E4[1024].
// ---------------------------------------------------------------------------
__global__ __launch_bounds__(256) void attn_comb3_k(
    const float* __restrict__ Pm, const float* __restrict__ Ps,
    const float* __restrict__ Pacc,
    __nv_bfloat16* __restrict__ Th, __nv_bfloat16* __restrict__ Tl)
{
    extern __shared__ float smc[];
    float* srow = smc;                 // 64*268 = 17152 floats
    float* E4 = smc + 64 * 268;        // 1024 floats
    int tid = threadIdx.x, warp = tid >> 5, lane = tid & 31;
    int qbase = blockIdx.x * 64;

    // phase 1: per-slot normalized chunk weights (coalesced float4 reads)
    {
        float4 mv = *(const float4*)&Pm[(size_t)qbase * 16 + tid * 4];
        float4 sv = *(const float4*)&Ps[(size_t)qbase * 16 + tid * 4];
        float M = fmaxf(fmaxf(mv.x, mv.y), fmaxf(mv.z, mv.w));
        float e0 = __expf(mv.x - M), e1 = __expf(mv.y - M);
        float e2 = __expf(mv.z - M), e3 = __expf(mv.w - M);
        float S = sv.x * e0 + sv.y * e1 + sv.z * e2 + sv.w * e3;
        float inv = 1.f / S;
        E4[tid * 4 + 0] = e0 * inv;
        E4[tid * 4 + 1] = e1 * inv;
        E4[tid * 4 + 2] = e2 * inv;
        E4[tid * 4 + 3] = e3 * inv;
    }
    __syncthreads();

    // phase 2: warp-cooperative merge, coalesced Pacc reads (lanes = hd)
    for (int s = warp; s < 256; s += 8) {
        int ql = s >> 2, h = s & 3;
        const float* P0 = Pacc + ((size_t)qbase * 16 + s * 4) * 64;
        float e0 = E4[s * 4], e1 = E4[s * 4 + 1], e2 = E4[s * 4 + 2], e3 = E4[s * 4 + 3];
        float vlo = P0[lane] * e0 + P0[64 + lane] * e1
                  + P0[128 + lane] * e2 + P0[192 + lane] * e3;
        float vhi = P0[32 + lane] * e0 + P0[96 + lane] * e1
                  + P0[160 + lane] * e2 + P0[224 + lane] * e3;
        srow[ql * 268 + h * 67 + lane] = vlo;
        srow[ql * 268 + h * 67 + 32 + lane] = vhi;
    }
    __syncthreads();

    // phase 3: coalesced transposed bf16x2 hi/lo writes
    uint32_t* TH32 = (uint32_t*)Th;
    uint32_t* TL32 = (uint32_t*)Tl;
#pragma unroll
    for (int it = 0; it < 32; it++) {
        int i = it * 256 + tid;
        int r = i >> 7, cp = i & 127;
        int c0 = cp * 2, c1 = c0 + 1;
        float v0 = srow[r * 268 + (c0 & 3) * 67 + (c0 >> 2)];
        float v1 = srow[r * 268 + (c1 & 3) * 67 + (c1 >> 2)];
        __nv_bfloat162 hp = __floats2bfloat162_rn(v0, v1);
        __nv_bfloat162 lp = __floats2bfloat162_rn(v0 - __bfloat162float(hp.x),
                                                  v1 - __bfloat162float(hp.y));
        size_t o = (size_t)(qbase + r) * 128 + cp;
        TH32[o] = *(uint32_t*)&hp;
        TL32[o] = *(uint32_t*)&lp;
    }
}

// ---------------------------------------------------------------------------
// Gathers / PEs / pool
// ---------------------------------------------------------------------------
__global__ void gather_trk(const float* __restrict__ tracks, float* __restrict__ o)
{
    int idx = blockIdx.x * 256 + threadIdx.x;
    if (idx >= 256 * P_TRK) return;
    int c = idx >> 14, p = idx & 16383;
    int bi = p >> 4, t = p & 15;
    o[idx] = tracks[bi * 4112 + (c + 1) * 16 + t];
}
__global__ void gather_det(const float* __restrict__ det, float* __restrict__ o)
{
    int idx = blockIdx.x * 256 + threadIdx.x;
    if (idx >= 256 * P_DET) return;
    int c = idx >> 12, p = idx & 4095;
    int b = p >> 10, m = p & 1023;
    o[idx] = det[b * 263168 + (c + 1) * 1024 + m];
}
__global__ void pe_trk_k(const float* __restrict__ tracks, float* __restrict__ pe)
{
    int idx = blockIdx.x * 256 + threadIdx.x;
    if (idx >= 256 * P_TRK) return;
    int c = idx >> 14, p = idx & 16383;
    int bi = p >> 4, t = p & 15;
    float pos = tracks[bi * 4112 + t];
    float dv = expf((float)(c & ~1) * (-9.210340371976184f / 256.f));
    float ang = pos * dv;
    pe[idx] = (c & 1) ? cosf(ang) : sinf(ang);
}
__global__ void pe_det_k(const float* __restrict__ det, float* __restrict__ pe)
{
    int idx = blockIdx.x * 256 + threadIdx.x;
    if (idx >= 256 * P_DET) return;
    int c = idx >> 12, p = idx & 4095;
    int b = p >> 10, m = p & 1023;
    float pos = det[b * 263168 + m];
    float dv = expf((float)(c & ~1) * (-9.210340371976184f / 256.f));
    float ang = pos * dv;
    pe[idx] = (c & 1) ? cosf(ang) : sinf(ang);
}
__global__ void pool_k(const float* __restrict__ x, float* __restrict__ td)
{
    int idx = blockIdx.x * 256 + threadIdx.x;
    if (idx >= 256 * P_TR) return;
    int c = idx >> 10, bi = idx & 1023;
    const float* p = x + c * P_TRK + bi * 16;
    float s = 0.f;
#pragma unroll
    for (int t = 0; t < 16; t++) s += p[t];
    td[c * P_TD + bi] = s * 0.0625f;
}

// ---------------------------------------------------------------------------
// scores / bins / log-domain Sinkhorn (R11 proven)
// ---------------------------------------------------------------------------
__global__ __launch_bounds__(256) void scores_k(
    const float* __restrict__ M01, float* __restrict__ Z0)
{
    __shared__ float As[16][64];
    __shared__ float Bs[16][64];
    int tid = threadIdx.x, tx = tid & 15, ty = tid >> 4;
    int b = blockIdx.z;
    int nc = blockIdx.y * 64, mc = blockIdx.x * 64;
    float acc[4][4] = {};
    for (int kc = 0; kc < 256; kc += 16) {
#pragma unroll
        for (int r = 0; r < 4; r++) {
            int e = tid + r * 256;
            int kl = e >> 6, nl = e & 63;
            As[kl][nl] = M01[(kc + kl) * P_TD + b * 256 + nc + nl];
        }
#pragma unroll
        for (int r = 0; r < 4; r++) {
            int e = tid + r * 256;
            int kl = e >> 6, ml = e & 63;
            Bs[kl][ml] = M01[(kc + kl) * P_TD + 1024 + b * 1024 + mc + ml];
        }
        __syncthreads();
#pragma unroll
        for (int kk = 0; kk < 16; kk++) {
            float a[4], bb[4];
#pragma unroll
            for (int i = 0; i < 4; i++) a[i] = As[kk][ty * 4 + i];
#pragma unroll
            for (int j = 0; j < 4; j++) bb[j] = Bs[kk][tx * 4 + j];
#pragma unroll
            for (int i = 0; i < 4; i++)
#pragma unroll
                for (int j = 0; j < 4; j++) acc[i][j] += a[i] * bb[j];
        }
        __syncthreads();
    }
#pragma unroll
    for (int i = 0; i < 4; i++) {
        int n = nc + ty * 4 + i;
#pragma unroll
        for (int j = 0; j < 4; j++) {
            int m = mc + tx * 4 + j;
            Z0[b * ZROW + n * 1025 + m] = acc[i][j] * 0.0625f;
        }
    }
}

__global__ void fill_bins(float* __restrict__ Z0, const float* __restrict__ alpha_p)
{
    float a = *alpha_p;
    int idx = blockIdx.x * 256 + threadIdx.x;
    if (idx < 1024) {
        int b = idx >> 8, i = idx & 255;
        Z0[b * ZROW + i * 1025 + 1024] = a;
    }
    int idx2 = idx - 1024;
    if (idx2 >= 0 && idx2 < 4100) {
        int b = idx2 / 1025, j = idx2 % 1025;
        Z0[b * ZROW + 256 * 1025 + j] = a;
    }
}

__global__ void zero_k(float* p, int n)
{
    int i = blockIdx.x * 256 + threadIdx.x;
    if (i < n) p[i] = 0.f;
}

__device__ __forceinline__ void lse_merge(float& m, float& s, float om, float os)
{
    float M = fmaxf(m, om);
    s = s * __expf(m - M) + os * __expf(om - M);
    m = M;
}

__device__ __forceinline__ void grid_bar(unsigned* cnt, unsigned target)
{
    __syncthreads();
    if (threadIdx.x == 0) {
        __threadfence();
        atomicAdd(cnt, 1u);
        volatile unsigned* vc = cnt;
        while (*vc < target * (unsigned)NBLK_SINK) {}
        __threadfence();
    }
    __syncthreads();
}

__global__ __launch_bounds__(256) void sink_fused_k(
    const float* __restrict__ Z0, float* __restrict__ u, float* __restrict__ v,
    unsigned* __restrict__ cnt)
{
    __shared__ float smm[8], sss[8];
    __shared__ float smm2[8][33], sss2[8][33];
    int tid = threadIdx.x;
    int w = tid >> 5, l = tid & 31;
    unsigned phase = 0;

    for (int it = 0; it < 100; it++) {
        for (int row = blockIdx.x; row < 1028; row += NBLK_SINK) {
            int b = row / 257, i = row % 257;
            const float* zr = Z0 + b * ZROW + i * 1025;
            const float* vb = v + b * 1025;
            float m = -1e30f, s = 0.f;
            for (int j = tid; j < 1025; j += 256) {
                float z = zr[j] + vb[j];
                if (z > m) { s = s * __expf(m - z) + 1.f; m = z; }
                else s += __expf(z - m);
            }
            for (int off = 16; off; off >>= 1) {
                float om = __shfl_down_sync(0xffffffffu, m, off);
                float os = __shfl_down_sync(0xffffffffu, s, off);
                lse_merge(m, s, om, os);
            }
            if (l == 0) { smm[w] = m; sss[w] = s; }
            __syncthreads();
            if (tid == 0) {
                m = smm[0]; s = sss[0];
                for (int k = 1; k < 8; k++) lse_merge(m, s, smm[k], sss[k]);
                float logmu = (i < 256) ? NORM_C : (NORM_C + LOG1024);
                u[row] = logmu - (m + __logf(s));
            }
            __syncthreads();
        }
        phase++; grid_bar(cnt, phase);

        for (int task = blockIdx.x; task < 132; task += NBLK_SINK) {
            int b = task / 33, jt = task % 33;
            int j = jt * 32 + l;
            float m = -1e30f, s = 0.f;
            if (j < 1025) {
                const float* zb = Z0 + b * ZROW;
                const float* ub = u + b * 257;
                for (int i = w; i < 257; i += 8) {
                    float z = zb[i * 1025 + j] + ub[i];
                    if (z > m) { s = s * __expf(m - z) + 1.f; m = z; }
                    else s += __expf(z - m);
                }
            }
            smm2[w][l] = m; sss2[w][l] = s;
            __syncthreads();
            if (w == 0 && j < 1025) {
                m = smm2[0][l]; s = sss2[0][l];
                for (int k = 1; k < 8; k++) lse_merge(m, s, smm2[k][l], sss2[k][l]);
                float lognu = (j < 1024) ? NORM_C : (NORM_C + LOG256);
                v[b * 1025 + j] = lognu - (m + __logf(s));
            }
            __syncthreads();
        }
        phase++; grid_bar(cnt, phase);
    }
}

__global__ void sink_out(const float* __restrict__ Z0, const float* __restrict__ u,
                         const float* __restrict__ v, float* __restrict__ out)
{
    int idx = blockIdx.x * 256 + threadIdx.x;
    if (idx >= 4 * ZROW) return;
    int b = idx / ZROW;
    int r = idx - b * ZROW;
    int i = r / 1025, j = r - i * 1025;
    out[idx] = Z0[idx] + u[b * 257 + i] + v[b * 1025 + j] - NORM_C;
}

// ---------------------------------------------------------------------------
// Host orchestration
// ---------------------------------------------------------------------------
typedef __nv_bfloat16 bf;

static void gemmN(const bf* Wh, const bf* Wl, const float* bias,
                  const bf* Xh, const bf* Xl, int xs,
                  const bf* X2h, const bf* X2l, int x2s,
                  const float* addp, int as, float* out, int os,
                  bf* oTh, bf* oTl, int ots,
                  int outOff, int O, int I, int Pcols, int relu)
{
    dim3 g(Pcols / 128, O / 128);
    gemm_bf2_k<<<g, 256, 98304>>>(Wh, Wl, bias, Xh, Xl, X2h, X2l, xs, x2s,
                                  addp, as, out, os, oTh, oTl, ots, outOff, I, relu);
}
static void tsplit(const float* X, int C, int P, bf* Th, bf* Tl)
{
    dim3 g(P / 32, C / 32);
    t_split_k<<<g, dim3(32, 8)>>>(X, P, Th, Tl, C);
}

#define OW_ENC1   0
#define OW_ENC2   65536
#define OW_FPW    131072
#define OW_FMW    917504
#define OW_FM1    1179648
#define OW_FM2    2228224
#define OW_GPW    2752512
#define OW_GMW    5111808
#define OW_GM1    5898240
#define OW_GM2    9043968
#define OW_FIN    10616832

extern "C" void kernel_launch(void* const* d_in, const int* in_sizes, int n_in,
                              void* d_out, int out_size)
{
    const float* detections = (const float*)d_in[0];
    const float* tracks     = (const float*)d_in[1];
    const float* enc_w1 = (const float*)d_in[2];
    const float* enc_b1 = (const float*)d_in[3];
    const float* enc_w2 = (const float*)d_in[4];
    const float* enc_b2 = (const float*)d_in[5];
    const float* fus_pw  = (const float*)d_in[6];
    const float* fus_pb  = (const float*)d_in[7];
    const float* fus_mw  = (const float*)d_in[8];
    const float* fus_mb  = (const float*)d_in[9];
    const float* fus_m1w = (const float*)d_in[10];
    const float* fus_m1b = (const float*)d_in[11];
    const float* fus_m2w = (const float*)d_in[12];
    const float* fus_m2b = (const float*)d_in[13];
    const float* gnn_pw  = (const float*)d_in[14];
    const float* gnn_pb  = (const float*)d_in[15];
    const float* gnn_mw  = (const float*)d_in[16];
    const float* gnn_mb  = (const float*)d_in[17];
    const float* gnn_m1w = (const float*)d_in[18];
    const float* gnn_m1b = (const float*)d_in[19];
    const float* gnn_m2w = (const float*)d_in[20];
    const float* gnn_m2b = (const float*)d_in[21];
    const float* final_w = (const float*)d_in[22];
    const float* final_b = (const float*)d_in[23];
    const float* bin_score = (const float*)d_in[24];
    float* out = (float*)d_out;

    cudaFuncSetAttribute(gemm_bf2_k, cudaFuncAttributeMaxDynamicSharedMemorySize, 98304);
    cudaFuncSetAttribute(attn_comb3_k, cudaFuncAttributeMaxDynamicSharedMemorySize, 72704);

    float* pool = nullptr;
    cudaGetSymbolAddress((void**)&pool, g_pool);
    size_t off = 0;
    auto carve = [&](size_t n) { float* p = pool + off; off += n; return p; };
    bf* WH       = (bf*)carve(5341184);
    bf* WL       = (bf*)carve(5341184);
    float* TRKIN = carve(4194304);
    float* DETIN = carve(1048576);
    float* TRKPE = carve(4194304);
    float* DETPE = carve(1048576);
    bf* TRKINT_H = (bf*)carve(2097152);
    bf* TRKINT_L = (bf*)carve(2097152);
    bf* DETINT_H = (bf*)carve(524288);
    bf* DETINT_L = (bf*)carve(524288);
    float* QKV   = carve(12582912);
    float* MSG   = carve(4194304);
    bf* MSGT_H   = (bf*)carve(2097152);
    bf* MSGT_L   = (bf*)carve(2097152);
    bf* MSG2T_H  = (bf*)carve(2097152);
    bf* MSG2T_L  = (bf*)carve(2097152);
    bf* TMP1T_H  = (bf*)carve(4194304);
    bf* TMP1T_L  = (bf*)carve(4194304);
    float* XA    = carve(4194304);
    float* XB    = carve(4194304);
    bf* XAT_H    = (bf*)carve(2097152);
    bf* XAT_L    = (bf*)carve(2097152);
    bf* XBT_H    = (bf*)carve(2097152);
    bf* XBT_L    = (bf*)carve(2097152);
    float* TDA   = carve(1310720);
    float* TDB   = carve(1310720);
    bf* TDAT_H   = (bf*)carve(655360);
    bf* TDAT_L   = (bf*)carve(655360);
    bf* TDBT_H   = (bf*)carve(655360);
    bf* TDBT_L   = (bf*)carve(655360);
    float* M01   = carve(1310720);
    float* Z0    = carve(1053700);
    float* U     = carve(1028);
    float* V     = carve(4100);
    float* CNT   = carve(4);
    float* PM    = carve(81920);
    float* PS    = carve(81920);
    float* PACC  = carve(5242880);

    WSplitArgs wa;
    const float* srcs[11] = {enc_w1, enc_w2, fus_pw, fus_mw, fus_m1w, fus_m2w,
                             gnn_pw, gnn_mw, gnn_m1w, gnn_m2w, final_w};
    int ns[11] = {65536, 65536, 786432, 262144, 1048576, 524288,
                  2359296, 786432, 3145728, 1572864, 65536};
    int ofs[11] = {OW_ENC1, OW_ENC2, OW_FPW, OW_FMW, OW_FM1, OW_FM2,
                   OW_GPW, OW_GMW, OW_GM1, OW_GM2, OW_FIN};
    for (int i = 0; i < 11; i++) { wa.src[i] = srcs[i]; wa.n[i] = ns[i]; wa.off[i] = ofs[i]; }
    wa.hi = WH; wa.lo = WL;
    w_split_k<<<dim3(12288, 11), 256>>>(wa);

    gather_trk<<<16384, 256>>>(tracks, TRKIN);
    gather_det<<<4096, 256>>>(detections, DETIN);
    tsplit(TRKIN, 256, P_TRK, TRKINT_H, TRKINT_L);
    gemmN(WH + OW_ENC1, WL + OW_ENC1, enc_b1, TRKINT_H, TRKINT_L, 256,
          nullptr, nullptr, 0, nullptr, 0, nullptr, 0,
          TMP1T_H, TMP1T_L, 256, 0, 256, 256, P_TRK, 1);
    tsplit(DETIN, 256, P_DET, DETINT_H, DETINT_L);
    pe_trk_k<<<16384, 256>>>(tracks, TRKPE);
    pe_det_k<<<4096, 256>>>(detections, DETPE);
    gemmN(WH + OW_ENC2, WL + OW_ENC2, enc_b2, TMP1T_H, TMP1T_L, 256,
          nullptr, nullptr, 0, TRKPE, P_TRK, XA, P_TRK,
          XAT_H, XAT_L, 256, 0, 256, 256, P_TRK, 0);
    gemmN(WH + OW_ENC1, WL + OW_ENC1, enc_b1, DETINT_H, DETINT_L, 256,
          nullptr, nullptr, 0, nullptr, 0, nullptr, 0,
          TMP1T_H, TMP1T_L, 256, 0, 256, 256, P_DET, 1);
    gemmN(WH + OW_ENC2, WL + OW_ENC2, enc_b2, TMP1T_H, TMP1T_L, 256,
          nullptr, nullptr, 0, DETPE, P_DET, TDA, P_TD,
          nullptr, nullptr, 0, 1024, 256, 256, P_DET, 0);

    float* x = XA; float* xo = XB;
    bf *xTh = XAT_H, *xTl = XAT_L, *xoTh = XBT_H, *xoTl = XBT_L;
    for (int l = 0; l < 4; l++) {
        gemmN(WH + OW_FPW + l * 196608, WL + OW_FPW + l * 196608, fus_pb + l * 768,
              xTh, xTl, 256, nullptr, nullptr, 0, nullptr, 0,
              QKV, P_TRK, nullptr, nullptr, 0, 0, 768, 256, P_TRK, 0);
        attn_fus_k<<<dim3(1, 4, 256), 64>>>(QKV, QKV + 256 * P_TRK, QKV + 512 * P_TRK, MSG);
        tsplit(MSG, 256, P_TRK, MSGT_H, MSGT_L);
        gemmN(WH + OW_FMW + l * 65536, WL + OW_FMW + l * 65536, fus_mb + l * 256,
              MSGT_H, MSGT_L, 256, nullptr, nullptr, 0, nullptr, 0,
              nullptr, 0, MSG2T_H, MSG2T_L, 256, 0, 256, 256, P_TRK, 0);
        gemmN(WH + OW_FM1 + l * 262144, WL + OW_FM1 + l * 262144, fus_m1b + l * 512,
              xTh, xTl, 256, MSG2T_H, MSG2T_L, 256, nullptr, 0,
              nullptr, 0, TMP1T_H, TMP1T_L, 512, 0, 512, 512, P_TRK, 1);
        gemmN(WH + OW_FM2 + l * 131072, WL + OW_FM2 + l * 131072, fus_m2b + l * 256,
              TMP1T_H, TMP1T_L, 512, nullptr, nullptr, 0, x, P_TRK,
              xo, P_TRK, xoTh, xoTl, 256, 0, 256, 512, P_TRK, 0);
        float* t = x; x = xo; xo = t;
        bf* th = xTh; xTh = xoTh; xoTh = th;
        bf* tl = xTl; xTl = xoTl; xoTl = tl;
    }
    pool_k<<<1024, 256>>>(x, TDA);
    tsplit(TDA, 256, P_TD, TDAT_H, TDAT_L);

    float* td = TDA; float* tdo = TDB;
    bf *tdTh = TDAT_H, *tdTl = TDAT_L, *tdoTh = TDBT_H, *tdoTl = TDBT_L;
    for (int l = 0; l < 12; l++) {
        int cross = l & 1;
        gemmN(WH + OW_GPW + l * 196608, WL + OW_GPW + l * 196608, gnn_pb + l * 768,
              tdTh, tdTl, 256, nullptr, nullptr, 0, nullptr, 0,
              QKV, P_TD, nullptr, nullptr, 0, 0, 768, 256, P_TD, 0);
        attn_part_k<<<dim3(20, 4, 16), 64>>>(QKV, cross, PM, PS, PACC);
        attn_comb3_k<<<80, 256, 72704>>>(PM, PS, PACC, MSGT_H, MSGT_L);
        gemmN(WH + OW_GMW + l * 65536, WL + OW_GMW + l * 65536, gnn_mb + l * 256,
              MSGT_H, MSGT_L, 256, nullptr, nullptr, 0, nullptr, 0,
              nullptr, 0, MSG2T_H, MSG2T_L, 256, 0, 256, 256, P_TD, 0);
        gemmN(WH + OW_GM1 + l * 262144, WL + OW_GM1 + l * 262144, gnn_m1b + l * 512,
              tdTh, tdTl, 256, MSG2T_H, MSG2T_L, 256, nullptr, 0,
              nullptr, 0, TMP1T_H, TMP1T_L, 512, 0, 512, 512, P_TD, 1);
        gemmN(WH + OW_GM2 + l * 131072, WL + OW_GM2 + l * 131072, gnn_m2b + l * 256,
              TMP1T_H, TMP1T_L, 512, nullptr, nullptr, 0, td, P_TD,
              tdo, P_TD, tdoTh, tdoTl, 256, 0, 256, 512, P_TD, 0);
        float* t = td; td = tdo; tdo = t;
        bf* th = tdTh; tdTh = tdoTh; tdoTh = th;
        bf* tl = tdTl; tdTl = tdoTl; tdoTl = tl;
    }

    gemmN(WH + OW_FIN, WL + OW_FIN, final_b, tdTh, tdTl, 256,
          nullptr, nullptr, 0, nullptr, 0, M01, P_TD,
          nullptr, nullptr, 0, 0, 256, 256, P_TD, 0);
    scores_k<<<dim3(16, 4, 4), 256>>>(M01, Z0);
    fill_bins<<<21, 256>>>(Z0, bin_score);
    zero_k<<<21, 256>>>(U, 5129);

    sink_fused_k<<<NBLK_SINK, 256>>>(Z0, U, V, (unsigned*)CNT);
    sink_out<<<(4 * ZROW + 255) / 256, 256>>>(Z0, U, V, out);
    (void)in_sizes; (void)n_in; (void)out_size;
}